// round 11
// baseline (speedup 1.0000x reference)
#include <cuda_runtime.h>
#include <cuda_fp16.h>
#include <math.h>

#define B 64
#define J 2048
#define N 32
#define D 16
#define ND 512
#define EPS 1e-7f

// u_hat fp16, routing layout: uint4 at (b*J+j)*64 + q, q = n*2+g, halves = d 8g..8g+7
__device__ __align__(16) uint4 g_u4[(size_t)B * J * 64];     // 128 MiB
// x fragments (for k1 mma): g_xsw[(j*8+bh)*32+lane] = uint2{a0,a2}, b = bh*8+gid
__device__ __align__(16) uint2 g_xsw[(size_t)J * 8 * 32];    // 4.2 MiB
__device__ __align__(16) float g_spart[3][B * ND];           // s accum [b][n*16+d]

// ---- helpers --------------------------------------------------------------
static __device__ __forceinline__ unsigned long long pk2(float a, float b) {
    unsigned long long v;
    asm("mov.b64 %0, {%1, %2};" : "=l"(v) : "f"(a), "f"(b));
    return v;
}
static __device__ __forceinline__ float2 upk2(unsigned long long v) {
    float2 f;
    asm("mov.b64 {%0, %1}, %2;" : "=f"(f.x), "=f"(f.y) : "l"(v));
    return f;
}
static __device__ __forceinline__ void fma2(unsigned long long& d,
                                            unsigned long long a,
                                            unsigned long long b) {
    asm("fma.rn.f32x2 %0, %1, %2, %0;" : "+l"(d) : "l"(a), "l"(b));
}
static __device__ __forceinline__ void redv2(float* p, float a, float b) {
    asm volatile("red.global.add.v2.f32 [%0], {%1, %2};"
                 :: "l"(p), "f"(a), "f"(b) : "memory");
}
static __device__ __forceinline__ void mma16816(
    float& d0, float& d1, float& d2, float& d3,
    unsigned a0, unsigned a1, unsigned a2, unsigned a3,
    unsigned b0, unsigned b1,
    float c0, float c1, float c2, float c3) {
    asm volatile(
        "mma.sync.aligned.m16n8k16.row.col.f32.f16.f16.f32 "
        "{%0,%1,%2,%3},{%4,%5,%6,%7},{%8,%9},{%10,%11,%12,%13};"
        : "=f"(d0), "=f"(d1), "=f"(d2), "=f"(d3)
        : "r"(a0), "r"(a1), "r"(a2), "r"(a3), "r"(b0), "r"(b1),
          "f"(c0), "f"(c1), "f"(c2), "f"(c3));
}

// ---------------------------------------------------------------------------
__global__ void cvt_x_zero_kernel(const float* __restrict__ x) {
    int o = blockIdx.x * blockDim.x + threadIdx.x;  // < 524288
    const int lane = o & 31;
    const int bh = (o >> 5) & 7;
    const int j = o >> 8;
    const int tig = lane & 3;
    const int gid = lane >> 2;
    const int b = bh * 8 + gid;

    const float* xp = x + ((size_t)(b * J + j) << 4);
    float2 f0 = *reinterpret_cast<const float2*>(xp + 2 * tig);
    float2 f1 = *reinterpret_cast<const float2*>(xp + 2 * tig + 8);
    __half2 h0 = __floats2half2_rn(f0.x, f0.y);
    __half2 h1 = __floats2half2_rn(f1.x, f1.y);
    uint2 out;
    out.x = *reinterpret_cast<unsigned*>(&h0);
    out.y = *reinterpret_cast<unsigned*>(&h1);
    g_xsw[o] = out;

    if (o < 3 * B * ND) ((float*)g_spart)[o] = 0.0f;
}

// ---------------------------------------------------------------------------
// k1: per j, compute u_hat tile [64b x 256r] via mma (W fp32 streamed, fresh
// fp16 convert in regs), accumulate s0 in running C accumulators (diff-trick
// store), transpose through smem to the routing layout, coalesced STG.128.
// grid (J/8, 2 r-halves), block 256 (8 warps); warp w: r in [rh*256+32w, +32).
// ---------------------------------------------------------------------------
__global__ void __launch_bounds__(256, 1)
k1_kernel(const float* __restrict__ Wf) {
    // tile[b][n_local][d] halves; b-pitch 264 halves (16n*16d=256, +8 pad)
    __shared__ __half tile[64 * 264];  // 33792 B

    const int tid = threadIdx.x;
    const int w = tid >> 5;
    const int lane = tid & 31;
    const int gid = lane >> 2;
    const int tig = lane & 3;
    const int rh = blockIdx.y;
    const int rbase = rh * 256 + 32 * w;

    float C[4][4][4];
#pragma unroll
    for (int nt = 0; nt < 4; ++nt)
#pragma unroll
        for (int mi = 0; mi < 4; ++mi)
#pragma unroll
            for (int e = 0; e < 4; ++e) C[nt][mi][e] = 0.0f;

    for (int jj = 0; jj < 8; ++jj) {
        const int j = blockIdx.x * 8 + jj;

        // W fp32 loads (coalesced ~512B per warp per nt)
        float2 F0[4], F1[4];
#pragma unroll
        for (int nt = 0; nt < 4; ++nt) {
            const int r = rbase + 8 * nt + gid;
            const float* wp = Wf + ((size_t)((r >> 4) * J + j)) * 256 + ((r & 15) << 4);
            F0[nt] = *reinterpret_cast<const float2*>(wp + 2 * tig);
            F1[nt] = *reinterpret_cast<const float2*>(wp + 2 * tig + 8);
        }

        // x fragments (coalesced from g_xsw)
        unsigned a[4][4];
#pragma unroll
        for (int mi = 0; mi < 4; ++mi) {
            uint2 xv0 = __ldg(&g_xsw[(size_t)(j * 8 + 2 * mi) * 32 + lane]);
            uint2 xv1 = __ldg(&g_xsw[(size_t)(j * 8 + 2 * mi + 1) * 32 + lane]);
            a[mi][0] = xv0.x;
            a[mi][1] = xv1.x;
            a[mi][2] = xv0.y;
            a[mi][3] = xv1.y;
        }

#pragma unroll
        for (int nt = 0; nt < 4; ++nt) {
            __half2 h0 = __floats2half2_rn(F0[nt].x, F0[nt].y);
            __half2 h1 = __floats2half2_rn(F1[nt].x, F1[nt].y);
            unsigned b0 = *reinterpret_cast<unsigned*>(&h0);
            unsigned b1 = *reinterpret_cast<unsigned*>(&h1);
            const int nl = 2 * w + (nt >> 1);           // n_local 0..15
            const int dd = 8 * (nt & 1) + 2 * tig;      // d 0..15 (even)
#pragma unroll
            for (int mi = 0; mi < 4; ++mi) {
                float d0, d1, d2, d3;
                mma16816(d0, d1, d2, d3,
                         a[mi][0], a[mi][1], a[mi][2], a[mi][3], b0, b1,
                         C[nt][mi][0], C[nt][mi][1], C[nt][mi][2], C[nt][mi][3]);
                __half2 u01 = __floats2half2_rn(d0 - C[nt][mi][0], d1 - C[nt][mi][1]);
                __half2 u23 = __floats2half2_rn(d2 - C[nt][mi][2], d3 - C[nt][mi][3]);
                C[nt][mi][0] = d0; C[nt][mi][1] = d1;
                C[nt][mi][2] = d2; C[nt][mi][3] = d3;
                const int brow = mi * 16 + gid;
                *reinterpret_cast<__half2*>(&tile[brow * 264 + nl * 16 + dd]) = u01;
                *reinterpret_cast<__half2*>(&tile[(brow + 8) * 264 + nl * 16 + dd]) = u23;
            }
        }
        __syncthreads();

        // coalesced write-out: 2048 uint4 per (block, j)
#pragma unroll
        for (int it = 0; it < 8; ++it) {
            const int idx = it * 256 + tid;     // 0..2047
            const int b = idx >> 5;
            const int ql = idx & 31;            // n_local*2 + g
            uint4 v = *reinterpret_cast<const uint4*>(
                &tile[b * 264 + (ql >> 1) * 16 + (ql & 1) * 8]);
            g_u4[(size_t)(b * J + j) * 64 + rh * 32 + ql] = v;
        }
        __syncthreads();
    }

    // flush s0 (C now holds sum over this block's 8 j)
#pragma unroll
    for (int nt = 0; nt < 4; ++nt) {
        const int r = rbase + 8 * nt + 2 * tig;
#pragma unroll
        for (int mi = 0; mi < 4; ++mi) {
            const int brow = mi * 16 + gid;
            redv2(&g_spart[0][brow * ND + r], C[nt][mi][0], C[nt][mi][1]);
            redv2(&g_spart[0][(brow + 8) * ND + r], C[nt][mi][2], C[nt][mi][3]);
        }
    }
}

// ---------------------------------------------------------------------------
// Routing pass: pure streaming, lane = n, no barriers in the main loop.
// grid (16 j-chunks, 64 b), block 256 (8 warps); warp handles 16 j.
// MODE 1: v = squash(s0/32); MODE 2: v = squash(s0/32)+squash(s1).
// ---------------------------------------------------------------------------
template <int MODE>
__global__ void __launch_bounds__(256, 3) route2_kernel() {
    __shared__ float red[8][512];  // [warp][d*32+n]

    const int tid = threadIdx.x;
    const int w = tid >> 5;
    const int lane = tid & 31;       // lane = n
    const int b = blockIdx.y;
    const int jbase = blockIdx.x * 128 + w * 16;

    // --- prologue: in-lane squash(s) -> vr ---------------------------------
    float vv[16];
#pragma unroll
    for (int d = 0; d < 16; ++d) vv[d] = 0.0f;
#pragma unroll
    for (int it = 0; it < MODE; ++it) {
        const float pre = (it == 0) ? (1.0f / 32.0f) : 1.0f;
        const float* sp = &g_spart[it][(b * 32 + lane) * 16];
        float sv[16];
        float p = 0.0f;
#pragma unroll
        for (int q = 0; q < 4; ++q) {
            float4 f = *reinterpret_cast<const float4*>(sp + 4 * q);
            sv[4 * q] = f.x * pre; sv[4 * q + 1] = f.y * pre;
            sv[4 * q + 2] = f.z * pre; sv[4 * q + 3] = f.w * pre;
        }
#pragma unroll
        for (int d = 0; d < 16; ++d) p = fmaf(sv[d], sv[d], p);
        p += EPS;
        float sc = sqrtf(p) / (1.0f + p);
#pragma unroll
        for (int d = 0; d < 16; ++d) vv[d] += sc * sv[d];
    }
    unsigned long long vr[8];
#pragma unroll
    for (int p = 0; p < 8; ++p) vr[p] = pk2(vv[2 * p], vv[2 * p + 1]);

    unsigned long long acc[8];
#pragma unroll
    for (int p = 0; p < 8; ++p) acc[p] = 0ull;

    const uint4* up = g_u4 + (size_t)(b * J + jbase) * 64;

    // depth-2 prefetch pipeline
    uint4 A0 = __ldg(&up[lane * 2]);
    uint4 A1 = __ldg(&up[lane * 2 + 1]);
    uint4 B0 = __ldg(&up[64 + lane * 2]);
    uint4 B1 = __ldg(&up[64 + lane * 2 + 1]);

#pragma unroll
    for (int k = 0; k < 16; ++k) {
        uint4 N0, N1;
        if (k < 14) {
            N0 = __ldg(&up[(k + 2) * 64 + lane * 2]);
            N1 = __ldg(&up[(k + 2) * 64 + lane * 2 + 1]);
        }
        // process (A0, A1)
        unsigned long long uv[8];
        {
            const __half2* pa = reinterpret_cast<const __half2*>(&A0);
            const __half2* pb = reinterpret_cast<const __half2*>(&A1);
#pragma unroll
            for (int p = 0; p < 4; ++p) {
                float2 fa = __half22float2(pa[p]);
                float2 fb = __half22float2(pb[p]);
                uv[p] = pk2(fa.x, fa.y);
                uv[4 + p] = pk2(fb.x, fb.y);
            }
        }
        unsigned long long t2 = 0ull;
#pragma unroll
        for (int p = 0; p < 8; ++p) fma2(t2, vr[p], uv[p]);
        float2 ft = upk2(t2);
        float t = ft.x + ft.y;

        float e = __expf(t);
        float sum = e;
#pragma unroll
        for (int s = 16; s > 0; s >>= 1)
            sum += __shfl_xor_sync(0xffffffffu, sum, s);
        float c = __fdividef(e, sum);

        unsigned long long c2 = pk2(c, c);
#pragma unroll
        for (int p = 0; p < 8; ++p) fma2(acc[p], c2, uv[p]);

        A0 = B0; A1 = B1;
        B0 = N0; B1 = N1;
    }

    // block reduction: red[w][d*32 + n] (conflict-free STS/LDS)
#pragma unroll
    for (int p = 0; p < 8; ++p) {
        float2 f = upk2(acc[p]);
        red[w][(2 * p) * 32 + lane] = f.x;
        red[w][(2 * p + 1) * 32 + lane] = f.y;
    }
    __syncthreads();

    {
        const int n = tid & 31;
        const int d = (tid >> 5) * 2;
        float s0 = 0.f, s1 = 0.f;
#pragma unroll
        for (int ww = 0; ww < 8; ++ww) {
            s0 += red[ww][d * 32 + n];
            s1 += red[ww][(d + 1) * 32 + n];
        }
        redv2(&g_spart[MODE][b * ND + n * 16 + d], s0, s1);
    }
}

// ---------------------------------------------------------------------------
__global__ void squash_out_kernel(float* __restrict__ out) {
    int t = blockIdx.x * blockDim.x + threadIdx.x;  // (b*32+n)
    const float* s = &g_spart[2][t * 16];
    float sv[16];
    float s2 = 0.0f;
#pragma unroll
    for (int d = 0; d < 16; ++d) {
        float val = s[d];
        sv[d] = val;
        s2 = fmaf(val, val, s2);
    }
    s2 += EPS;
    float sc = sqrtf(s2) / (1.0f + s2);
#pragma unroll
    for (int d = 0; d < 16; ++d) out[t * 16 + d] = sc * sv[d];
}

// ---------------------------------------------------------------------------
extern "C" void kernel_launch(void* const* d_in, const int* in_sizes, int n_in,
                              void* d_out, int out_size) {
    const float* x = (const float*)d_in[0];  // [B, J, 16]
    const float* W = (const float*)d_in[1];  // [N, J, D, 16]
    float* out = (float*)d_out;              // [B, N, D]

    cvt_x_zero_kernel<<<2048, 256>>>(x);
    k1_kernel<<<dim3(256, 2), 256>>>(W);
    route2_kernel<1><<<dim3(16, 64), 256>>>();
    route2_kernel<2><<<dim3(16, 64), 256>>>();
    squash_out_kernel<<<16, 128>>>(out);
}

// round 12
// speedup vs baseline: 1.0404x; 1.0404x over previous
#include <cuda_runtime.h>
#include <cuda_fp16.h>
#include <math.h>

#define B 64
#define J 2048
#define N 32
#define D 16
#define ND 512
#define EPS 1e-7f

// u_hat fp16, routing layout: uint4 at (b*J+j)*64 + q, q = n*2+g, halves = d 8g..8g+7
__device__ __align__(16) uint4 g_u4[(size_t)B * J * 64];     // 128 MiB
// x fragments (for k1 mma): g_xsw[(j*8+bh)*32+lane] = uint2{a0,a2}, b = bh*8+gid
__device__ __align__(16) uint2 g_xsw[(size_t)J * 8 * 32];    // 4.2 MiB
__device__ __align__(16) float g_spart[3][B * ND];           // s accum [b][n*16+d]

// ---- helpers --------------------------------------------------------------
static __device__ __forceinline__ unsigned long long pk2(float a, float b) {
    unsigned long long v;
    asm("mov.b64 %0, {%1, %2};" : "=l"(v) : "f"(a), "f"(b));
    return v;
}
static __device__ __forceinline__ float2 upk2(unsigned long long v) {
    float2 f;
    asm("mov.b64 {%0, %1}, %2;" : "=f"(f.x), "=f"(f.y) : "l"(v));
    return f;
}
static __device__ __forceinline__ void fma2(unsigned long long& d,
                                            unsigned long long a,
                                            unsigned long long b) {
    asm("fma.rn.f32x2 %0, %1, %2, %0;" : "+l"(d) : "l"(a), "l"(b));
}
static __device__ __forceinline__ void redv2(float* p, float a, float b) {
    asm volatile("red.global.add.v2.f32 [%0], {%1, %2};"
                 :: "l"(p), "f"(a), "f"(b) : "memory");
}
static __device__ __forceinline__ void mma16816(
    float& d0, float& d1, float& d2, float& d3,
    unsigned a0, unsigned a1, unsigned a2, unsigned a3,
    unsigned b0, unsigned b1,
    float c0, float c1, float c2, float c3) {
    asm volatile(
        "mma.sync.aligned.m16n8k16.row.col.f32.f16.f16.f32 "
        "{%0,%1,%2,%3},{%4,%5,%6,%7},{%8,%9},{%10,%11,%12,%13};"
        : "=f"(d0), "=f"(d1), "=f"(d2), "=f"(d3)
        : "r"(a0), "r"(a1), "r"(a2), "r"(a3), "r"(b0), "r"(b1),
          "f"(c0), "f"(c1), "f"(c2), "f"(c3));
}

// ---------------------------------------------------------------------------
__global__ void cvt_x_zero_kernel(const float* __restrict__ x) {
    int o = blockIdx.x * blockDim.x + threadIdx.x;  // < 524288
    const int lane = o & 31;
    const int bh = (o >> 5) & 7;
    const int j = o >> 8;
    const int tig = lane & 3;
    const int gid = lane >> 2;
    const int b = bh * 8 + gid;

    const float* xp = x + ((size_t)(b * J + j) << 4);
    float2 f0 = *reinterpret_cast<const float2*>(xp + 2 * tig);
    float2 f1 = *reinterpret_cast<const float2*>(xp + 2 * tig + 8);
    __half2 h0 = __floats2half2_rn(f0.x, f0.y);
    __half2 h1 = __floats2half2_rn(f1.x, f1.y);
    uint2 out;
    out.x = *reinterpret_cast<unsigned*>(&h0);
    out.y = *reinterpret_cast<unsigned*>(&h1);
    g_xsw[o] = out;

    if (o < 3 * B * ND) ((float*)g_spart)[o] = 0.0f;
}

// ---------------------------------------------------------------------------
// k1: per j, compute u_hat tile [64b x 256r] via mma (W fp32 streamed, fp16
// convert in regs), s0 fused via running-accumulator diff, smem transpose to
// routing layout, coalesced STG.128. 2 CTAs/SM, cross-j W prefetch.
// grid (512 j-chunks of 4, 2 r-halves), block 256 (8 warps).
// ---------------------------------------------------------------------------
__global__ void __launch_bounds__(256, 2)
k1_kernel(const float* __restrict__ Wf) {
    // tile[b][n_local][d] halves; b-pitch 264 halves (256 + 8 pad)
    __shared__ __half tile[64 * 264];  // 33792 B

    const int tid = threadIdx.x;
    const int w = tid >> 5;
    const int lane = tid & 31;
    const int gid = lane >> 2;
    const int tig = lane & 3;
    const int rh = blockIdx.y;
    const int rbase = rh * 256 + 32 * w;
    const int j0 = blockIdx.x * 4;

    float C[4][4][4];
#pragma unroll
    for (int nt = 0; nt < 4; ++nt)
#pragma unroll
        for (int mi = 0; mi < 4; ++mi)
#pragma unroll
            for (int e = 0; e < 4; ++e) C[nt][mi][e] = 0.0f;

    float2 F0[2][4], F1[2][4];

#define LOADW(jv, buf)                                                         \
    {                                                                          \
        _Pragma("unroll") for (int nt = 0; nt < 4; ++nt) {                     \
            const int r = rbase + 8 * nt + gid;                                \
            const float* wp =                                                  \
                Wf + ((size_t)((r >> 4) * J + (jv))) * 256 + ((r & 15) << 4);  \
            F0[buf][nt] = *reinterpret_cast<const float2*>(wp + 2 * tig);      \
            F1[buf][nt] = *reinterpret_cast<const float2*>(wp + 2 * tig + 8);  \
        }                                                                      \
    }

    LOADW(j0, 0);

#pragma unroll
    for (int jj = 0; jj < 4; ++jj) {
        const int cur = jj & 1;
        const int j = j0 + jj;

        // prefetch next j's W first (flies over compute + barriers + STG)
        if (jj < 3) LOADW(j + 1, cur ^ 1);

        // x fragments (L1/L2-resident)
        unsigned a[4][4];
#pragma unroll
        for (int mi = 0; mi < 4; ++mi) {
            uint2 xv0 = __ldg(&g_xsw[(size_t)(j * 8 + 2 * mi) * 32 + lane]);
            uint2 xv1 = __ldg(&g_xsw[(size_t)(j * 8 + 2 * mi + 1) * 32 + lane]);
            a[mi][0] = xv0.x;
            a[mi][1] = xv1.x;
            a[mi][2] = xv0.y;
            a[mi][3] = xv1.y;
        }

#pragma unroll
        for (int nt = 0; nt < 4; ++nt) {
            __half2 h0 = __floats2half2_rn(F0[cur][nt].x, F0[cur][nt].y);
            __half2 h1 = __floats2half2_rn(F1[cur][nt].x, F1[cur][nt].y);
            unsigned b0 = *reinterpret_cast<unsigned*>(&h0);
            unsigned b1 = *reinterpret_cast<unsigned*>(&h1);
            const int nl = 2 * w + (nt >> 1);           // n_local 0..15
            const int dd = 8 * (nt & 1) + 2 * tig;      // d (even)
#pragma unroll
            for (int mi = 0; mi < 4; ++mi) {
                float d0, d1, d2, d3;
                mma16816(d0, d1, d2, d3,
                         a[mi][0], a[mi][1], a[mi][2], a[mi][3], b0, b1,
                         C[nt][mi][0], C[nt][mi][1], C[nt][mi][2], C[nt][mi][3]);
                __half2 u01 = __floats2half2_rn(d0 - C[nt][mi][0], d1 - C[nt][mi][1]);
                __half2 u23 = __floats2half2_rn(d2 - C[nt][mi][2], d3 - C[nt][mi][3]);
                C[nt][mi][0] = d0; C[nt][mi][1] = d1;
                C[nt][mi][2] = d2; C[nt][mi][3] = d3;
                const int brow = mi * 16 + gid;
                *reinterpret_cast<__half2*>(&tile[brow * 264 + nl * 16 + dd]) = u01;
                *reinterpret_cast<__half2*>(&tile[(brow + 8) * 264 + nl * 16 + dd]) = u23;
            }
        }
        __syncthreads();

        // coalesced write-out: 2048 uint4 per (block, j)
#pragma unroll
        for (int it = 0; it < 8; ++it) {
            const int idx = it * 256 + tid;     // 0..2047
            const int b = idx >> 5;
            const int ql = idx & 31;            // n_local*2 + g
            uint4 v = *reinterpret_cast<const uint4*>(
                &tile[b * 264 + (ql >> 1) * 16 + (ql & 1) * 8]);
            g_u4[(size_t)(b * J + j) * 64 + rh * 32 + ql] = v;
        }
        __syncthreads();
    }
#undef LOADW

    // flush s0 (C holds sum over this block's 4 j)
#pragma unroll
    for (int nt = 0; nt < 4; ++nt) {
        const int r = rbase + 8 * nt + 2 * tig;
#pragma unroll
        for (int mi = 0; mi < 4; ++mi) {
            const int brow = mi * 16 + gid;
            redv2(&g_spart[0][brow * ND + r], C[nt][mi][0], C[nt][mi][1]);
            redv2(&g_spart[0][(brow + 8) * ND + r], C[nt][mi][2], C[nt][mi][3]);
        }
    }
}

// ---------------------------------------------------------------------------
// Routing pass: pure streaming, lane = n, no barriers in the main loop.
// grid (16 j-chunks, 64 b), block 256 (8 warps); warp handles 16 j.
// MODE 1: v = squash(s0/32); MODE 2: v = squash(s0/32)+squash(s1).
// ---------------------------------------------------------------------------
template <int MODE>
__global__ void __launch_bounds__(256, 3) route2_kernel() {
    __shared__ float red[8][512];  // [warp][d*32+n]

    const int tid = threadIdx.x;
    const int w = tid >> 5;
    const int lane = tid & 31;       // lane = n
    const int b = blockIdx.y;
    const int jbase = blockIdx.x * 128 + w * 16;

    // --- prologue: in-lane squash(s) -> vr ---------------------------------
    float vv[16];
#pragma unroll
    for (int d = 0; d < 16; ++d) vv[d] = 0.0f;
#pragma unroll
    for (int it = 0; it < MODE; ++it) {
        const float pre = (it == 0) ? (1.0f / 32.0f) : 1.0f;
        const float* sp = &g_spart[it][(b * 32 + lane) * 16];
        float sv[16];
        float p = 0.0f;
#pragma unroll
        for (int q = 0; q < 4; ++q) {
            float4 f = *reinterpret_cast<const float4*>(sp + 4 * q);
            sv[4 * q] = f.x * pre; sv[4 * q + 1] = f.y * pre;
            sv[4 * q + 2] = f.z * pre; sv[4 * q + 3] = f.w * pre;
        }
#pragma unroll
        for (int d = 0; d < 16; ++d) p = fmaf(sv[d], sv[d], p);
        p += EPS;
        float sc = sqrtf(p) / (1.0f + p);
#pragma unroll
        for (int d = 0; d < 16; ++d) vv[d] += sc * sv[d];
    }
    unsigned long long vr[8];
#pragma unroll
    for (int p = 0; p < 8; ++p) vr[p] = pk2(vv[2 * p], vv[2 * p + 1]);

    unsigned long long acc[8];
#pragma unroll
    for (int p = 0; p < 8; ++p) acc[p] = 0ull;

    const uint4* up = g_u4 + (size_t)(b * J + jbase) * 64;

    // depth-2 prefetch pipeline
    uint4 A0 = __ldg(&up[lane * 2]);
    uint4 A1 = __ldg(&up[lane * 2 + 1]);
    uint4 B0 = __ldg(&up[64 + lane * 2]);
    uint4 B1 = __ldg(&up[64 + lane * 2 + 1]);

#pragma unroll
    for (int k = 0; k < 16; ++k) {
        uint4 N0, N1;
        if (k < 14) {
            N0 = __ldg(&up[(k + 2) * 64 + lane * 2]);
            N1 = __ldg(&up[(k + 2) * 64 + lane * 2 + 1]);
        }
        unsigned long long uv[8];
        {
            const __half2* pa = reinterpret_cast<const __half2*>(&A0);
            const __half2* pb = reinterpret_cast<const __half2*>(&A1);
#pragma unroll
            for (int p = 0; p < 4; ++p) {
                float2 fa = __half22float2(pa[p]);
                float2 fb = __half22float2(pb[p]);
                uv[p] = pk2(fa.x, fa.y);
                uv[4 + p] = pk2(fb.x, fb.y);
            }
        }
        unsigned long long t2 = 0ull;
#pragma unroll
        for (int p = 0; p < 8; ++p) fma2(t2, vr[p], uv[p]);
        float2 ft = upk2(t2);
        float t = ft.x + ft.y;

        float e = __expf(t);
        float sum = e;
#pragma unroll
        for (int s = 16; s > 0; s >>= 1)
            sum += __shfl_xor_sync(0xffffffffu, sum, s);
        float c = __fdividef(e, sum);

        unsigned long long c2 = pk2(c, c);
#pragma unroll
        for (int p = 0; p < 8; ++p) fma2(acc[p], c2, uv[p]);

        A0 = B0; A1 = B1;
        B0 = N0; B1 = N1;
    }

    // block reduction: red[w][d*32 + n] (conflict-free STS/LDS)
#pragma unroll
    for (int p = 0; p < 8; ++p) {
        float2 f = upk2(acc[p]);
        red[w][(2 * p) * 32 + lane] = f.x;
        red[w][(2 * p + 1) * 32 + lane] = f.y;
    }
    __syncthreads();

    {
        const int n = tid & 31;
        const int d = (tid >> 5) * 2;
        float s0 = 0.f, s1 = 0.f;
#pragma unroll
        for (int ww = 0; ww < 8; ++ww) {
            s0 += red[ww][d * 32 + n];
            s1 += red[ww][(d + 1) * 32 + n];
        }
        redv2(&g_spart[MODE][b * ND + n * 16 + d], s0, s1);
    }
}

// ---------------------------------------------------------------------------
__global__ void squash_out_kernel(float* __restrict__ out) {
    int t = blockIdx.x * blockDim.x + threadIdx.x;  // (b*32+n)
    const float* s = &g_spart[2][t * 16];
    float sv[16];
    float s2 = 0.0f;
#pragma unroll
    for (int d = 0; d < 16; ++d) {
        float val = s[d];
        sv[d] = val;
        s2 = fmaf(val, val, s2);
    }
    s2 += EPS;
    float sc = sqrtf(s2) / (1.0f + s2);
#pragma unroll
    for (int d = 0; d < 16; ++d) out[t * 16 + d] = sc * sv[d];
}

// ---------------------------------------------------------------------------
extern "C" void kernel_launch(void* const* d_in, const int* in_sizes, int n_in,
                              void* d_out, int out_size) {
    const float* x = (const float*)d_in[0];  // [B, J, 16]
    const float* W = (const float*)d_in[1];  // [N, J, D, 16]
    float* out = (float*)d_out;              // [B, N, D]

    cvt_x_zero_kernel<<<2048, 256>>>(x);
    k1_kernel<<<dim3(512, 2), 256>>>(W);
    route2_kernel<1><<<dim3(16, 64), 256>>>();
    route2_kernel<2><<<dim3(16, 64), 256>>>();
    squash_out_kernel<<<16, 128>>>(out);
}

// round 13
// speedup vs baseline: 1.2493x; 1.2008x over previous
#include <cuda_runtime.h>
#include <cuda_fp16.h>
#include <math.h>

#define B 64
#define J 2048
#define N 32
#define D 16
#define ND 512
#define EPS 1e-7f

// u_hat fp16, routing layout: uint4 at (b*J+j)*64 + q, q = n*2+g, halves = d 8g..8g+7
__device__ __align__(16) uint4 g_u4[(size_t)B * J * 64];     // 128 MiB
// x fragments (for k1 mma): g_xsw[(j*8+bh)*32+lane] = uint2{a0,a2}, b = bh*8+gid
__device__ __align__(16) uint2 g_xsw[(size_t)J * 8 * 32];    // 4.2 MiB
__device__ __align__(16) float g_spart[3][B * ND];           // s accum [b][n*16+d]

// ---- helpers --------------------------------------------------------------
static __device__ __forceinline__ unsigned long long pk2(float a, float b) {
    unsigned long long v;
    asm("mov.b64 %0, {%1, %2};" : "=l"(v) : "f"(a), "f"(b));
    return v;
}
static __device__ __forceinline__ float2 upk2(unsigned long long v) {
    float2 f;
    asm("mov.b64 {%0, %1}, %2;" : "=f"(f.x), "=f"(f.y) : "l"(v));
    return f;
}
static __device__ __forceinline__ void fma2(unsigned long long& d,
                                            unsigned long long a,
                                            unsigned long long b) {
    asm("fma.rn.f32x2 %0, %1, %2, %0;" : "+l"(d) : "l"(a), "l"(b));
}
static __device__ __forceinline__ void redv2(float* p, float a, float b) {
    asm volatile("red.global.add.v2.f32 [%0], {%1, %2};"
                 :: "l"(p), "f"(a), "f"(b) : "memory");
}
static __device__ __forceinline__ void mma16816(
    float& d0, float& d1, float& d2, float& d3,
    unsigned a0, unsigned a1, unsigned a2, unsigned a3,
    unsigned b0, unsigned b1,
    float c0, float c1, float c2, float c3) {
    asm volatile(
        "mma.sync.aligned.m16n8k16.row.col.f32.f16.f16.f32 "
        "{%0,%1,%2,%3},{%4,%5,%6,%7},{%8,%9},{%10,%11,%12,%13};"
        : "=f"(d0), "=f"(d1), "=f"(d2), "=f"(d3)
        : "r"(a0), "r"(a1), "r"(a2), "r"(a3), "r"(b0), "r"(b1),
          "f"(c0), "f"(c1), "f"(c2), "f"(c3));
}

// ---------------------------------------------------------------------------
__global__ void cvt_x_zero_kernel(const float* __restrict__ x) {
    int o = blockIdx.x * blockDim.x + threadIdx.x;  // < 524288
    const int lane = o & 31;
    const int bh = (o >> 5) & 7;
    const int j = o >> 8;
    const int tig = lane & 3;
    const int gid = lane >> 2;
    const int b = bh * 8 + gid;

    const float* xp = x + ((size_t)(b * J + j) << 4);
    float2 f0 = *reinterpret_cast<const float2*>(xp + 2 * tig);
    float2 f1 = *reinterpret_cast<const float2*>(xp + 2 * tig + 8);
    __half2 h0 = __floats2half2_rn(f0.x, f0.y);
    __half2 h1 = __floats2half2_rn(f1.x, f1.y);
    uint2 out;
    out.x = *reinterpret_cast<unsigned*>(&h0);
    out.y = *reinterpret_cast<unsigned*>(&h1);
    g_xsw[o] = out;

    if (o < 3 * B * ND) ((float*)g_spart)[o] = 0.0f;
}

// ---------------------------------------------------------------------------
// k1: per j, u_hat tile [64b x 256r] via mma; W streamed fp32 with __ldcs
// (evict-first: don't pollute L2, u_hat write-allocations survive).
// s0 fused via running-accumulator diff; smem transpose; coalesced STG.128.
// grid (2 r-halves FAST, 512 j-chunks SLOW) so both halves of a j are
// schedule-adjacent. 2 CTAs/SM, cross-j W prefetch.
// ---------------------------------------------------------------------------
__global__ void __launch_bounds__(256, 2)
k1_kernel(const float* __restrict__ Wf) {
    __shared__ __half tile[64 * 264];  // 33792 B

    const int tid = threadIdx.x;
    const int w = tid >> 5;
    const int lane = tid & 31;
    const int gid = lane >> 2;
    const int tig = lane & 3;
    const int rh = blockIdx.x;          // FAST dim
    const int rbase = rh * 256 + 32 * w;
    const int j0 = blockIdx.y * 4;      // SLOW dim

    float C[4][4][4];
#pragma unroll
    for (int nt = 0; nt < 4; ++nt)
#pragma unroll
        for (int mi = 0; mi < 4; ++mi)
#pragma unroll
            for (int e = 0; e < 4; ++e) C[nt][mi][e] = 0.0f;

    float2 F0[2][4], F1[2][4];

#define LOADW(jv, buf)                                                         \
    {                                                                          \
        _Pragma("unroll") for (int nt = 0; nt < 4; ++nt) {                     \
            const int r = rbase + 8 * nt + gid;                                \
            const float* wp =                                                  \
                Wf + ((size_t)((r >> 4) * J + (jv))) * 256 + ((r & 15) << 4);  \
            F0[buf][nt] = __ldcs(reinterpret_cast<const float2*>(wp + 2 * tig));\
            F1[buf][nt] = __ldcs(reinterpret_cast<const float2*>(wp + 2 * tig + 8));\
        }                                                                      \
    }

    LOADW(j0, 0);

#pragma unroll
    for (int jj = 0; jj < 4; ++jj) {
        const int cur = jj & 1;
        const int j = j0 + jj;

        if (jj < 3) LOADW(j + 1, cur ^ 1);

        unsigned a[4][4];
#pragma unroll
        for (int mi = 0; mi < 4; ++mi) {
            uint2 xv0 = __ldg(&g_xsw[(size_t)(j * 8 + 2 * mi) * 32 + lane]);
            uint2 xv1 = __ldg(&g_xsw[(size_t)(j * 8 + 2 * mi + 1) * 32 + lane]);
            a[mi][0] = xv0.x;
            a[mi][1] = xv1.x;
            a[mi][2] = xv0.y;
            a[mi][3] = xv1.y;
        }

#pragma unroll
        for (int nt = 0; nt < 4; ++nt) {
            __half2 h0 = __floats2half2_rn(F0[cur][nt].x, F0[cur][nt].y);
            __half2 h1 = __floats2half2_rn(F1[cur][nt].x, F1[cur][nt].y);
            unsigned b0 = *reinterpret_cast<unsigned*>(&h0);
            unsigned b1 = *reinterpret_cast<unsigned*>(&h1);
            const int nl = 2 * w + (nt >> 1);
            const int dd = 8 * (nt & 1) + 2 * tig;
#pragma unroll
            for (int mi = 0; mi < 4; ++mi) {
                float d0, d1, d2, d3;
                mma16816(d0, d1, d2, d3,
                         a[mi][0], a[mi][1], a[mi][2], a[mi][3], b0, b1,
                         C[nt][mi][0], C[nt][mi][1], C[nt][mi][2], C[nt][mi][3]);
                __half2 u01 = __floats2half2_rn(d0 - C[nt][mi][0], d1 - C[nt][mi][1]);
                __half2 u23 = __floats2half2_rn(d2 - C[nt][mi][2], d3 - C[nt][mi][3]);
                C[nt][mi][0] = d0; C[nt][mi][1] = d1;
                C[nt][mi][2] = d2; C[nt][mi][3] = d3;
                const int brow = mi * 16 + gid;
                *reinterpret_cast<__half2*>(&tile[brow * 264 + nl * 16 + dd]) = u01;
                *reinterpret_cast<__half2*>(&tile[(brow + 8) * 264 + nl * 16 + dd]) = u23;
            }
        }
        __syncthreads();

#pragma unroll
        for (int it = 0; it < 8; ++it) {
            const int idx = it * 256 + tid;
            const int b = idx >> 5;
            const int ql = idx & 31;
            uint4 v = *reinterpret_cast<const uint4*>(
                &tile[b * 264 + (ql >> 1) * 16 + (ql & 1) * 8]);
            g_u4[(size_t)(b * J + j) * 64 + rh * 32 + ql] = v;
        }
        __syncthreads();
    }
#undef LOADW

#pragma unroll
    for (int nt = 0; nt < 4; ++nt) {
        const int r = rbase + 8 * nt + 2 * tig;
#pragma unroll
        for (int mi = 0; mi < 4; ++mi) {
            const int brow = mi * 16 + gid;
            redv2(&g_spart[0][brow * ND + r], C[nt][mi][0], C[nt][mi][1]);
            redv2(&g_spart[0][(brow + 8) * ND + r], C[nt][mi][2], C[nt][mi][3]);
        }
    }
}

// ---------------------------------------------------------------------------
// Routing pass: pure streaming, lane = n, no barriers in the main loop.
// MODE 1 reads j DESCENDING (hits k1's freshest L2 lines first);
// MODE 2 reads j ASCENDING with __ldcs (hits route<1>'s tail, evicts after use).
// grid (16 j-chunks, 64 b), block 256 (8 warps); warp handles 16 j.
// ---------------------------------------------------------------------------
template <int MODE>
__global__ void __launch_bounds__(256, 3) route2_kernel() {
    __shared__ float red[8][512];  // [warp][d*32+n]

    const int tid = threadIdx.x;
    const int w = tid >> 5;
    const int lane = tid & 31;       // lane = n
    const int b = blockIdx.y;
    const int jc = (MODE == 1) ? (15 - (int)blockIdx.x) : (int)blockIdx.x;
    const int jbase = jc * 128 + w * 16;

    // --- prologue: in-lane squash(s) -> vr ---------------------------------
    float vv[16];
#pragma unroll
    for (int d = 0; d < 16; ++d) vv[d] = 0.0f;
#pragma unroll
    for (int it = 0; it < MODE; ++it) {
        const float pre = (it == 0) ? (1.0f / 32.0f) : 1.0f;
        const float* sp = &g_spart[it][(b * 32 + lane) * 16];
        float sv[16];
        float p = 0.0f;
#pragma unroll
        for (int q = 0; q < 4; ++q) {
            float4 f = *reinterpret_cast<const float4*>(sp + 4 * q);
            sv[4 * q] = f.x * pre; sv[4 * q + 1] = f.y * pre;
            sv[4 * q + 2] = f.z * pre; sv[4 * q + 3] = f.w * pre;
        }
#pragma unroll
        for (int d = 0; d < 16; ++d) p = fmaf(sv[d], sv[d], p);
        p += EPS;
        float sc = sqrtf(p) / (1.0f + p);
#pragma unroll
        for (int d = 0; d < 16; ++d) vv[d] += sc * sv[d];
    }
    unsigned long long vr[8];
#pragma unroll
    for (int p = 0; p < 8; ++p) vr[p] = pk2(vv[2 * p], vv[2 * p + 1]);

    unsigned long long acc[8];
#pragma unroll
    for (int p = 0; p < 8; ++p) acc[p] = 0ull;

    const uint4* up = g_u4 + (size_t)(b * J + jbase) * 64;

    // j index within the warp's 16, direction by MODE
#define JOFF(k) ((MODE == 1) ? (15 - (k)) : (k))
#define LDU(ptr) ((MODE == 2) ? __ldcs(ptr) : __ldg(ptr))

    // depth-2 prefetch pipeline
    uint4 A0 = LDU(&up[JOFF(0) * 64 + lane * 2]);
    uint4 A1 = LDU(&up[JOFF(0) * 64 + lane * 2 + 1]);
    uint4 B0 = LDU(&up[JOFF(1) * 64 + lane * 2]);
    uint4 B1 = LDU(&up[JOFF(1) * 64 + lane * 2 + 1]);

#pragma unroll
    for (int k = 0; k < 16; ++k) {
        uint4 N0, N1;
        if (k < 14) {
            N0 = LDU(&up[JOFF(k + 2) * 64 + lane * 2]);
            N1 = LDU(&up[JOFF(k + 2) * 64 + lane * 2 + 1]);
        }
        unsigned long long uv[8];
        {
            const __half2* pa = reinterpret_cast<const __half2*>(&A0);
            const __half2* pb = reinterpret_cast<const __half2*>(&A1);
#pragma unroll
            for (int p = 0; p < 4; ++p) {
                float2 fa = __half22float2(pa[p]);
                float2 fb = __half22float2(pb[p]);
                uv[p] = pk2(fa.x, fa.y);
                uv[4 + p] = pk2(fb.x, fb.y);
            }
        }
        unsigned long long t2 = 0ull;
#pragma unroll
        for (int p = 0; p < 8; ++p) fma2(t2, vr[p], uv[p]);
        float2 ft = upk2(t2);
        float t = ft.x + ft.y;

        float e = __expf(t);
        float sum = e;
#pragma unroll
        for (int s = 16; s > 0; s >>= 1)
            sum += __shfl_xor_sync(0xffffffffu, sum, s);
        float c = __fdividef(e, sum);

        unsigned long long c2 = pk2(c, c);
#pragma unroll
        for (int p = 0; p < 8; ++p) fma2(acc[p], c2, uv[p]);

        A0 = B0; A1 = B1;
        B0 = N0; B1 = N1;
    }
#undef JOFF
#undef LDU

    // block reduction: red[w][d*32 + n]
#pragma unroll
    for (int p = 0; p < 8; ++p) {
        float2 f = upk2(acc[p]);
        red[w][(2 * p) * 32 + lane] = f.x;
        red[w][(2 * p + 1) * 32 + lane] = f.y;
    }
    __syncthreads();

    {
        const int n = tid & 31;
        const int d = (tid >> 5) * 2;
        float s0 = 0.f, s1 = 0.f;
#pragma unroll
        for (int ww = 0; ww < 8; ++ww) {
            s0 += red[ww][d * 32 + n];
            s1 += red[ww][(d + 1) * 32 + n];
        }
        redv2(&g_spart[MODE][b * ND + n * 16 + d], s0, s1);
    }
}

// ---------------------------------------------------------------------------
__global__ void squash_out_kernel(float* __restrict__ out) {
    int t = blockIdx.x * blockDim.x + threadIdx.x;  // (b*32+n)
    const float* s = &g_spart[2][t * 16];
    float sv[16];
    float s2 = 0.0f;
#pragma unroll
    for (int d = 0; d < 16; ++d) {
        float val = s[d];
        sv[d] = val;
        s2 = fmaf(val, val, s2);
    }
    s2 += EPS;
    float sc = sqrtf(s2) / (1.0f + s2);
#pragma unroll
    for (int d = 0; d < 16; ++d) out[t * 16 + d] = sc * sv[d];
}

// ---------------------------------------------------------------------------
extern "C" void kernel_launch(void* const* d_in, const int* in_sizes, int n_in,
                              void* d_out, int out_size) {
    const float* x = (const float*)d_in[0];  // [B, J, 16]
    const float* W = (const float*)d_in[1];  // [N, J, D, 16]
    float* out = (float*)d_out;              // [B, N, D]

    cvt_x_zero_kernel<<<2048, 256>>>(x);
    k1_kernel<<<dim3(2, 512), 256>>>(W);
    route2_kernel<1><<<dim3(16, 64), 256>>>();
    route2_kernel<2><<<dim3(16, 64), 256>>>();
    squash_out_kernel<<<16, 128>>>(out);
}